// round 16
// baseline (speedup 1.0000x reference)
#include <cuda_runtime.h>
#include <cuda_bf16.h>
#include <math.h>
#include <stdint.h>

// Problem constants
#define B_     2
#define N_     1024
#define DIM_   1024
#define HEADS_ 8
#define HD_    128
#define L_     4096   // m * nc
#define M_DOCS 4

// ---------------------------------------------------------------------------
// Scratch (__device__ globals; allocation-free rule)
// ---------------------------------------------------------------------------
__device__ __nv_bfloat16 g_xh [(B_*N_) * DIM_];
__device__ __nv_bfloat16 g_xl [(B_*N_) * DIM_];
__device__ __nv_bfloat16 g_ch [(B_*L_) * DIM_];
__device__ __nv_bfloat16 g_cl [(B_*L_) * DIM_];
__device__ __nv_bfloat16 g_oh [(B_*N_) * DIM_];   // attn output, split hi
__device__ __nv_bfloat16 g_ol [(B_*N_) * DIM_];   // attn output, split lo
// weights transposed to [N,K]
__device__ __nv_bfloat16 g_wqh [DIM_ * DIM_];
__device__ __nv_bfloat16 g_wql [DIM_ * DIM_];
__device__ __nv_bfloat16 g_wkvh[(2*DIM_) * DIM_];
__device__ __nv_bfloat16 g_wkvl[(2*DIM_) * DIM_];
__device__ __nv_bfloat16 g_woh [DIM_ * DIM_];
__device__ __nv_bfloat16 g_wol [DIM_ * DIM_];

// attention operands
__device__ __nv_bfloat16 g_qb [(B_*N_) * DIM_];   // Q plain bf16
__device__ __nv_bfloat16 g_kb [(B_*L_) * DIM_];   // K plain bf16
__device__ __nv_bfloat16 g_vrh[(B_*L_) * DIM_];   // V row-major hi
__device__ __nv_bfloat16 g_vrl[(B_*L_) * DIM_];   // V row-major lo

// ---------------------------------------------------------------------------
// PTX helpers — ONLY non-'a' features (compute_103 PTX: no tcgen05).
// ---------------------------------------------------------------------------
#define CP_ASYNC16(dst, src) \
    asm volatile("cp.async.cg.shared.global [%0], [%1], 16;\n" \
                 :: "r"(dst), "l"(src) : "memory")
#define CP_ASYNC_COMMIT()  asm volatile("cp.async.commit_group;\n" ::: "memory")
#define CP_ASYNC_WAIT1()   asm volatile("cp.async.wait_group 1;\n" ::: "memory")
#define CP_ASYNC_WAIT0()   asm volatile("cp.async.wait_group 0;\n" ::: "memory")

#define LDSM_X4(r0, r1, r2, r3, a) \
    asm volatile("ldmatrix.sync.aligned.m8n8.x4.shared.b16 {%0,%1,%2,%3}, [%4];" \
                 : "=r"(r0), "=r"(r1), "=r"(r2), "=r"(r3) : "r"(a))

#define LDSM_X4_T(r0, r1, r2, r3, a) \
    asm volatile("ldmatrix.sync.aligned.m8n8.x4.trans.shared.b16 {%0,%1,%2,%3}, [%4];" \
                 : "=r"(r0), "=r"(r1), "=r"(r2), "=r"(r3) : "r"(a))

__device__ __forceinline__ uint32_t smem_u32(const void* p) {
    uint32_t a;
    asm("{ .reg .u64 t; cvta.to.shared.u64 t, %1; cvt.u32.u64 %0, t; }"
        : "=r"(a) : "l"(p));
    return a;
}

// D += A @ B^T : m16n8k16, bf16 in, fp32 accum (layout validated R8/R10)
__device__ __forceinline__ void mma16816(float* d, const uint32_t* a,
                                         const uint32_t* b) {
    asm volatile(
        "mma.sync.aligned.m16n8k16.row.col.f32.bf16.bf16.f32 "
        "{%0,%1,%2,%3}, {%4,%5,%6,%7}, {%8,%9}, {%0,%1,%2,%3};"
        : "+f"(d[0]), "+f"(d[1]), "+f"(d[2]), "+f"(d[3])
        : "r"(a[0]), "r"(a[1]), "r"(a[2]), "r"(a[3]), "r"(b[0]), "r"(b[1]));
}

__device__ __forceinline__ uint32_t pack_bf16(float a, float b) {
    __nv_bfloat162 t = __float22bfloat162_rn(make_float2(a, b));
    return *(uint32_t*)&t;
}

// ---------------------------------------------------------------------------
// Conversion kernels — merged: 2 launches total
// ---------------------------------------------------------------------------
// split both x (2M) and ctx (8M) in one grid-strided launch
__global__ void conv_split_xc(const float* __restrict__ x,
                              const float* __restrict__ ctx,
                              __nv_bfloat16* __restrict__ xh,
                              __nv_bfloat16* __restrict__ xl,
                              __nv_bfloat16* __restrict__ ch,
                              __nv_bfloat16* __restrict__ cl)
{
    const int tx = B_ * N_ * DIM_;
    const int tc = B_ * L_ * DIM_;
    int i = blockIdx.x * blockDim.x + threadIdx.x;
    if (i < tx) {
        float v = x[i];
        __nv_bfloat16 hi = __float2bfloat16(v);
        xh[i] = hi;
        xl[i] = __float2bfloat16(v - __bfloat162float(hi));
    } else if (i < tx + tc) {
        int j = i - tx;
        float v = ctx[j];
        __nv_bfloat16 hi = __float2bfloat16(v);
        ch[j] = hi;
        cl[j] = __float2bfloat16(v - __bfloat162float(hi));
    }
}

// all three weight transposes (Wq 1024 tiles, Wkv 2048, Wout 1024) in one launch
__global__ void conv_w_t3(const float* __restrict__ Wq,
                          const float* __restrict__ Wkv,
                          const float* __restrict__ Wout,
                          __nv_bfloat16* __restrict__ wqh,
                          __nv_bfloat16* __restrict__ wql,
                          __nv_bfloat16* __restrict__ wkvh,
                          __nv_bfloat16* __restrict__ wkvl,
                          __nv_bfloat16* __restrict__ woh,
                          __nv_bfloat16* __restrict__ wol)
{
    __shared__ float t[32][33];
    int id = blockIdx.x;
    const float* W; __nv_bfloat16 *Wh, *Wl; int N, tile;
    if (id < 1024)      { W = Wq;   Wh = wqh;  Wl = wql;  N = DIM_;     tile = id; }
    else if (id < 3072) { W = Wkv;  Wh = wkvh; Wl = wkvl; N = 2 * DIM_; tile = id - 1024; }
    else                { W = Wout; Wh = woh;  Wl = wol;  N = DIM_;     tile = id - 3072; }
    const int K = DIM_;
    int nx = N / 32;
    int n0 = (tile % nx) * 32, k0 = (tile / nx) * 32;
    int tx = threadIdx.x, ty = threadIdx.y;
    #pragma unroll
    for (int i = 0; i < 32; i += 8)
        t[ty + i][tx] = W[(size_t)(k0 + ty + i) * N + n0 + tx];
    __syncthreads();
    #pragma unroll
    for (int i = 0; i < 32; i += 8) {
        float v = t[tx][ty + i];
        __nv_bfloat16 hi = __float2bfloat16(v);
        size_t o = (size_t)(n0 + ty + i) * K + k0 + tx;
        Wh[o] = hi;
        Wl[o] = __float2bfloat16(v - __bfloat162float(hi));
    }
}

// ---------------------------------------------------------------------------
// GEMM core (unchanged from R14 — passing)
// ---------------------------------------------------------------------------
#define GM_BM  128
#define GM_BN  128
#define GM_BK  64
#define GM_LDA 72
#define GM_STAGE_ELEMS ((GM_BM + GM_BN) * GM_LDA)
#define GM_SMEM_DYN (2 * GM_STAGE_ELEMS * 2)

__device__ __forceinline__ void gemm_core(
    const __nv_bfloat16* __restrict__ Ah, const __nv_bfloat16* __restrict__ Al,
    const __nv_bfloat16* __restrict__ Bh, const __nv_bfloat16* __restrict__ Bl,
    const float* __restrict__ bias, float* __restrict__ C,
    __nv_bfloat16* __restrict__ Cb,
    __nv_bfloat16* __restrict__ vrh, __nv_bfloat16* __restrict__ vrl,
    int M, int N, int K, int mode, int npasses, int m0, int n0,
    __nv_bfloat16* dsm)
{
    const int tid   = threadIdx.x;
    const int wid   = tid >> 5;
    const int lane  = tid & 31;
    const int g     = lane >> 2;
    const int t4    = lane & 3;
    const int warpM = wid & 3;
    const int warpN = wid >> 2;
    const int KB = K * 2;
    const int kchunks = K / GM_BK;
    const int NCHUNK = npasses * kchunks;

    const uint32_t smem_base = smem_u32(dsm);

    const uint32_t aOff = (uint32_t)(warpM * 32 + (lane & 15)) * (GM_LDA * 2)
                        + ((lane >> 4) << 3) * 2;
    const uint32_t bOff = (uint32_t)(warpN * 64 + ((lane & 16) >> 1) + (lane & 7))
                        * (GM_LDA * 2) + ((lane & 8) ? 16 : 0);

    float acc[2][8][4];
    #pragma unroll
    for (int mi = 0; mi < 2; mi++)
        #pragma unroll
        for (int ni = 0; ni < 8; ni++)
            #pragma unroll
            for (int r = 0; r < 4; r++) acc[mi][ni][r] = 0.f;

    auto load_tile = [&](int s, int c) {
        int pass = c / kchunks;
        int kc   = c - pass * kchunks;
        const char* Asrc = (const char*)((pass < 2) ? Ah : Al)
                         + (size_t)m0 * KB + (size_t)kc * (GM_BK * 2);
        const char* Bsrc = (const char*)((pass == 1) ? Bl : Bh)
                         + (size_t)n0 * KB + (size_t)kc * (GM_BK * 2);
        uint32_t As = smem_base + s * (GM_STAGE_ELEMS * 2);
        uint32_t Bs = As + GM_BM * GM_LDA * 2;
        #pragma unroll
        for (int i = 0; i < 8; i++) {
            int u = tid + i * 256;
            if (i < 4) {
                int row = u >> 3, ch = u & 7;
                CP_ASYNC16(As + row * (GM_LDA * 2) + ch * 16,
                           Asrc + (size_t)row * KB + ch * 16);
            } else {
                int v = u - 1024;
                int row = v >> 3, ch = v & 7;
                CP_ASYNC16(Bs + row * (GM_LDA * 2) + ch * 16,
                           Bsrc + (size_t)row * KB + ch * 16);
            }
        }
        CP_ASYNC_COMMIT();
    };

    load_tile(0, 0);

    for (int c = 0; c < NCHUNK; c++) {
        if (c + 1 < NCHUNK) {
            load_tile((c + 1) & 1, c + 1);
            CP_ASYNC_WAIT1();
        } else {
            CP_ASYNC_WAIT0();
        }
        __syncthreads();

        uint32_t As = smem_base + (c & 1) * (GM_STAGE_ELEMS * 2);
        uint32_t Bs = As + GM_BM * GM_LDA * 2;
        uint32_t aAddr = As + aOff;
        uint32_t bAddr = Bs + bOff;

        #pragma unroll
        for (int kk = 0; kk < GM_BK; kk += 16) {
            uint32_t af[2][4], bfr[8][2];
            #pragma unroll
            for (int mi = 0; mi < 2; mi++)
                LDSM_X4(af[mi][0], af[mi][1], af[mi][2], af[mi][3],
                        aAddr + kk * 2 + mi * 16 * (GM_LDA * 2));
            #pragma unroll
            for (int pr = 0; pr < 4; pr++)
                LDSM_X4(bfr[2*pr][0], bfr[2*pr][1], bfr[2*pr+1][0], bfr[2*pr+1][1],
                        bAddr + kk * 2 + pr * 16 * (GM_LDA * 2));
            #pragma unroll
            for (int mi = 0; mi < 2; mi++)
                #pragma unroll
                for (int ni = 0; ni < 8; ni++)
                    mma16816(acc[mi][ni], af[mi], bfr[ni]);
        }
        __syncthreads();
    }

    #pragma unroll
    for (int mi = 0; mi < 2; mi++) {
        int rowA = m0 + warpM * 32 + mi * 16 + g;
        #pragma unroll
        for (int ni = 0; ni < 8; ni++) {
            int col = n0 + warpN * 64 + ni * 8 + 2 * t4;
            #pragma unroll
            for (int half = 0; half < 2; half++) {
                int row = rowA + half * 8;
                float v0 = acc[mi][ni][half * 2 + 0];
                float v1 = acc[mi][ni][half * 2 + 1];
                if (mode == 0) {
                    *(float2*)(C + (size_t)row * N + col) =
                        make_float2(v0 + bias[col], v1 + bias[col + 1]);
                } else if (mode == 1) {
                    *(uint32_t*)(Cb + (size_t)row * N + col) = pack_bf16(v0, v1);
                } else {
                    size_t off = (size_t)row * N + col;
                    __nv_bfloat16 h0 = __float2bfloat16(v0);
                    __nv_bfloat16 h1 = __float2bfloat16(v1);
                    __nv_bfloat162 hp; hp.x = h0; hp.y = h1;
                    *(uint32_t*)(vrh + off) = *(uint32_t*)&hp;
                    *(uint32_t*)(vrl + off) =
                        pack_bf16(v0 - __bfloat162float(h0),
                                  v1 - __bfloat162float(h1));
                }
            }
        }
    }
}

__global__ __launch_bounds__(256, 2)
void gemm_mma(const __nv_bfloat16* __restrict__ Ah,
              const __nv_bfloat16* __restrict__ Al,
              const __nv_bfloat16* __restrict__ Bh,
              const __nv_bfloat16* __restrict__ Bl,
              const float* __restrict__ bias, float* __restrict__ C,
              int M, int N, int K, int npasses)
{
    extern __shared__ __align__(16) __nv_bfloat16 dsm[];
    gemm_core(Ah, Al, Bh, Bl, bias, C, nullptr, nullptr, nullptr,
              M, N, K, 0, npasses, blockIdx.y * GM_BM, blockIdx.x * GM_BN, dsm);
}

__global__ __launch_bounds__(256, 2)
void gemm_qkv(const __nv_bfloat16* __restrict__ xh,
              const __nv_bfloat16* __restrict__ xl,
              const __nv_bfloat16* __restrict__ ch,
              const __nv_bfloat16* __restrict__ cl,
              const __nv_bfloat16* __restrict__ wqh,
              const __nv_bfloat16* __restrict__ wql,
              const __nv_bfloat16* __restrict__ wkvh,
              const __nv_bfloat16* __restrict__ wkvl,
              __nv_bfloat16* __restrict__ qb,
              __nv_bfloat16* __restrict__ kb,
              __nv_bfloat16* __restrict__ vrh,
              __nv_bfloat16* __restrict__ vrl)
{
    extern __shared__ __align__(16) __nv_bfloat16 dsm[];
    int id = blockIdx.x;
    if (id < 512) {                     // V: 3-pass, split row-major out
        int m0 = (id >> 3) * GM_BM, n0 = (id & 7) * GM_BN;
        gemm_core(ch, cl, wkvh + (size_t)DIM_ * DIM_, wkvl + (size_t)DIM_ * DIM_,
                  nullptr, nullptr, nullptr, vrh, vrl,
                  B_ * L_, DIM_, DIM_, 2, 3, m0, n0, dsm);
    } else if (id < 1024) {             // K: 1-pass, plain bf16
        int t = id - 512;
        int m0 = (t >> 3) * GM_BM, n0 = (t & 7) * GM_BN;
        gemm_core(ch, cl, wkvh, wkvl, nullptr, nullptr, kb, nullptr, nullptr,
                  B_ * L_, DIM_, DIM_, 1, 1, m0, n0, dsm);
    } else {                            // Q: 1-pass, plain bf16
        int t = id - 1024;
        int m0 = (t >> 3) * GM_BM, n0 = (t & 7) * GM_BN;
        gemm_core(xh, xl, wqh, wql, nullptr, nullptr, qb, nullptr, nullptr,
                  B_ * N_, DIM_, DIM_, 1, 1, m0, n0, dsm);
    }
}

// ---------------------------------------------------------------------------
// Flash attention, occupancy 2: single-buffered K/V (87 KB smem) with a
// phase-offset pipeline — K(t+1) loads during softmax+PV(t), V(t+1) during
// QK(t+1).  cp.async groups FIFO: pending is always <= {older, newer};
// wait_group 1 drains the older one.
// ---------------------------------------------------------------------------
#define AT_LDQ 136
#define AT_LDK 136
#define AT_LDV 136
#define AT_SMEM ((128*AT_LDQ + 3*64*AT_LDK) * 2)   // 87040 B

__global__ __launch_bounds__(256, 2)
void ca_attn_mma(const __nv_bfloat16* __restrict__ qb,
                 const __nv_bfloat16* __restrict__ kb,
                 const __nv_bfloat16* __restrict__ vrh,
                 const __nv_bfloat16* __restrict__ vrl,
                 const float* __restrict__ sims,
                 const float* __restrict__ beta_p,
                 __nv_bfloat16* __restrict__ Oh,
                 __nv_bfloat16* __restrict__ Ol)
{
    extern __shared__ __align__(16) __nv_bfloat16 smattn[];
    const uint32_t sQ  = smem_u32(smattn);
    const uint32_t sK  = sQ  + 128 * AT_LDQ * 2;
    const uint32_t sVh = sK  + 64 * AT_LDK * 2;
    const uint32_t sVl = sVh + 64 * AT_LDV * 2;

    const int qt = blockIdx.x, h = blockIdx.y, b = blockIdx.z;
    const int tid = threadIdx.x, wid = tid >> 5, lane = tid & 31;
    const int g = lane >> 2, t4 = lane & 3;
    const float beta = beta_p[0];
    const int qrow0 = b * N_ + qt * 128;

    const uint32_t qOff = (uint32_t)(wid * 16 + (lane & 15)) * (AT_LDQ * 2)
                        + ((lane >> 4) << 3) * 2;
    const uint32_t kOff = (uint32_t)(((lane & 16) >> 1) + (lane & 7)) * (AT_LDK * 2)
                        + ((lane & 8) ? 16 : 0);
    const uint32_t vOffT = (uint32_t)(((lane & 8) ? 8 : 0) + (lane & 7)) * (AT_LDV * 2)
                         + ((lane & 16) ? 16 : 0);

    // Q load (group 0)
    #pragma unroll
    for (int i = 0; i < 8; i++) {
        int u = tid + i * 256, r = u >> 4, ch = u & 15;
        CP_ASYNC16(sQ + r * (AT_LDQ * 2) + ch * 16,
                   (const char*)qb + ((size_t)(qrow0 + r) * DIM_ + h * HD_) * 2 + ch * 16);
    }
    CP_ASYNC_COMMIT();

    auto load_k = [&](int kt) {
        const size_t krow0 = (size_t)(b * L_ + kt * 64);
        #pragma unroll
        for (int i = 0; i < 4; i++) {
            int u = tid + i * 256, r = u >> 4, ch = u & 15;
            CP_ASYNC16(sK + r * (AT_LDK * 2) + ch * 16,
                       (const char*)kb + ((krow0 + r) * DIM_ + h * HD_) * 2 + ch * 16);
        }
        CP_ASYNC_COMMIT();
    };
    auto load_v = [&](int kt) {
        const size_t krow0 = (size_t)(b * L_ + kt * 64);
        #pragma unroll
        for (int i = 0; i < 4; i++) {
            int u = tid + i * 256, r = u >> 4, ch = u & 15;
            CP_ASYNC16(sVh + r * (AT_LDV * 2) + ch * 16,
                       (const char*)vrh + ((krow0 + r) * DIM_ + h * HD_) * 2 + ch * 16);
        }
        #pragma unroll
        for (int i = 0; i < 4; i++) {
            int u = tid + i * 256, r = u >> 4, ch = u & 15;
            CP_ASYNC16(sVl + r * (AT_LDV * 2) + ch * 16,
                       (const char*)vrl + ((krow0 + r) * DIM_ + h * HD_) * 2 + ch * 16);
        }
        CP_ASYNC_COMMIT();
    };

    load_k(0);   // group 1
    load_v(0);   // group 2

    float o[16][4];
    #pragma unroll
    for (int nj = 0; nj < 16; nj++)
        #pragma unroll
        for (int r = 0; r < 4; r++) o[nj][r] = 0.f;
    float m0r = -3.0e38f, m1r = -3.0e38f, l0r = 0.f, l1r = 0.f;

    for (int kt = 0; kt < 64; kt++) {
        // wait K(kt): pending = {K(kt), V(kt)} (t=0: {Q,K0,V0}; Q,K0 older)
        CP_ASYNC_WAIT1();
        __syncthreads();

        // ---- S = Q @ K^T ----
        float s[8][4];
        #pragma unroll
        for (int nj = 0; nj < 8; nj++)
            #pragma unroll
            for (int r = 0; r < 4; r++) s[nj][r] = 0.f;

        #pragma unroll
        for (int kk = 0; kk < 128; kk += 16) {
            uint32_t af[4], bfr[8][2];
            LDSM_X4(af[0], af[1], af[2], af[3], sQ + qOff + kk * 2);
            #pragma unroll
            for (int pr = 0; pr < 4; pr++)
                LDSM_X4(bfr[2*pr][0], bfr[2*pr][1], bfr[2*pr+1][0], bfr[2*pr+1][1],
                        sK + kOff + kk * 2 + pr * 16 * (AT_LDK * 2));
            #pragma unroll
            for (int nj = 0; nj < 8; nj++)
                mma16816(s[nj], af, bfr[nj]);
        }
        __syncthreads();                 // all warps done reading K
        if (kt + 1 < 64) load_k(kt + 1); // overwrite K buffer (overlaps softmax+PV)

        // ---- online softmax (registers only) ----
        const float simv = sims[b * M_DOCS + (kt >> 4)] * beta;
        float lg[8][4];
        float mt0 = -3.0e38f, mt1 = -3.0e38f;
        #pragma unroll
        for (int nj = 0; nj < 8; nj++) {
            lg[nj][0] = s[nj][0] * 0.03125f + simv;
            lg[nj][1] = s[nj][1] * 0.03125f + simv;
            lg[nj][2] = s[nj][2] * 0.03125f + simv;
            lg[nj][3] = s[nj][3] * 0.03125f + simv;
            mt0 = fmaxf(mt0, fmaxf(lg[nj][0], lg[nj][1]));
            mt1 = fmaxf(mt1, fmaxf(lg[nj][2], lg[nj][3]));
        }
        mt0 = fmaxf(mt0, __shfl_xor_sync(0xffffffffu, mt0, 1, 4));
        mt0 = fmaxf(mt0, __shfl_xor_sync(0xffffffffu, mt0, 2, 4));
        mt1 = fmaxf(mt1, __shfl_xor_sync(0xffffffffu, mt1, 1, 4));
        mt1 = fmaxf(mt1, __shfl_xor_sync(0xffffffffu, mt1, 2, 4));
        float mn0 = fmaxf(m0r, mt0), mn1 = fmaxf(m1r, mt1);
        float c0 = __expf(m0r - mn0), c1 = __expf(m1r - mn1);
        m0r = mn0; m1r = mn1; l0r *= c0; l1r *= c1;
        #pragma unroll
        for (int nj = 0; nj < 16; nj++) {
            o[nj][0] *= c0; o[nj][1] *= c0;
            o[nj][2] *= c1; o[nj][3] *= c1;
        }

        uint32_t ph01[8], ph23[8], pl01[8], pl23[8];
        #pragma unroll
        for (int nj = 0; nj < 8; nj++) {
            float p0 = __expf(lg[nj][0] - mn0), p1 = __expf(lg[nj][1] - mn0);
            float p2 = __expf(lg[nj][2] - mn1), p3 = __expf(lg[nj][3] - mn1);
            l0r += p0 + p1; l1r += p2 + p3;
            __nv_bfloat162 h01 = __float22bfloat162_rn(make_float2(p0, p1));
            __nv_bfloat162 h23 = __float22bfloat162_rn(make_float2(p2, p3));
            float2 b01 = __bfloat1622float2(h01);
            float2 b23 = __bfloat1622float2(h23);
            ph01[nj] = *(uint32_t*)&h01;
            ph23[nj] = *(uint32_t*)&h23;
            pl01[nj] = pack_bf16(p0 - b01.x, p1 - b01.y);
            pl23[nj] = pack_bf16(p2 - b23.x, p3 - b23.y);
        }

        // wait V(kt): pending = {V(kt), K(kt+1)}  (kt=63: {V63} only)
        if (kt + 1 < 64) CP_ASYNC_WAIT1(); else CP_ASYNC_WAIT0();
        __syncthreads();

        // ---- O += ph*Vh + ph*Vl + pl*Vh ----
        #pragma unroll
        for (int kbi = 0; kbi < 4; kbi++) {
            uint32_t ah[4] = { ph01[2*kbi], ph23[2*kbi], ph01[2*kbi+1], ph23[2*kbi+1] };
            uint32_t al[4] = { pl01[2*kbi], pl23[2*kbi], pl01[2*kbi+1], pl23[2*kbi+1] };
            #pragma unroll
            for (int pr = 0; pr < 8; pr++) {
                uint32_t bh2[2], bh2b[2], bl2[2], bl2b[2];
                uint32_t adrH = sVh + vOffT + (kbi * 16) * (AT_LDV * 2) + pr * 32;
                uint32_t adrL = sVl + vOffT + (kbi * 16) * (AT_LDV * 2) + pr * 32;
                LDSM_X4_T(bh2[0], bh2[1], bh2b[0], bh2b[1], adrH);
                LDSM_X4_T(bl2[0], bl2[1], bl2b[0], bl2b[1], adrL);
                mma16816(o[2*pr],     ah, bh2);
                mma16816(o[2*pr],     ah, bl2);
                mma16816(o[2*pr],     al, bh2);
                mma16816(o[2*pr + 1], ah, bh2b);
                mma16816(o[2*pr + 1], ah, bl2b);
                mma16816(o[2*pr + 1], al, bh2b);
            }
        }
        __syncthreads();                 // all warps done reading V
        if (kt + 1 < 64) load_v(kt + 1); // overwrite V buffer (overlaps next QK)
    }

    l0r += __shfl_xor_sync(0xffffffffu, l0r, 1, 4);
    l0r += __shfl_xor_sync(0xffffffffu, l0r, 2, 4);
    l1r += __shfl_xor_sync(0xffffffffu, l1r, 1, 4);
    l1r += __shfl_xor_sync(0xffffffffu, l1r, 2, 4);
    float inv0 = 1.0f / l0r, inv1 = 1.0f / l1r;

    int row0 = qrow0 + wid * 16 + g;
    #pragma unroll
    for (int nj = 0; nj < 16; nj++) {
        int col = nj * 8 + 2 * t4;
        #pragma unroll
        for (int half = 0; half < 2; half++) {
            float v0 = o[nj][half * 2 + 0] * (half ? inv1 : inv0);
            float v1 = o[nj][half * 2 + 1] * (half ? inv1 : inv0);
            size_t off = (size_t)(row0 + half * 8) * DIM_ + h * HD_ + col;
            __nv_bfloat162 hi2;
            hi2.x = __float2bfloat16(v0);
            hi2.y = __float2bfloat16(v1);
            *(uint32_t*)(Oh + off) = *(uint32_t*)&hi2;
            *(uint32_t*)(Ol + off) =
                pack_bf16(v0 - __bfloat162float(hi2.x),
                          v1 - __bfloat162float(hi2.y));
        }
    }
}

// ---------------------------------------------------------------------------
extern "C" void kernel_launch(void* const* d_in, const int* in_sizes, int n_in,
                              void* d_out, int out_size)
{
    const float* x    = (const float*)d_in[0];
    const float* ctx  = (const float*)d_in[1];
    const float* sims = (const float*)d_in[2];
    const float* Wq   = (const float*)d_in[3];
    const float* Wkv  = (const float*)d_in[4];
    const float* beta = (const float*)d_in[5];
    const float* Wout = (const float*)d_in[6];
    const float* bout = (const float*)d_in[7];
    float* out = (float*)d_out;

    __nv_bfloat16 *xh, *xl, *ch, *cl, *oh, *ol;
    __nv_bfloat16 *wqh, *wql, *wkvh, *wkvl, *woh, *wol;
    __nv_bfloat16 *qb, *kbp, *vrh, *vrl;
    cudaGetSymbolAddress((void**)&xh,  g_xh);
    cudaGetSymbolAddress((void**)&xl,  g_xl);
    cudaGetSymbolAddress((void**)&ch,  g_ch);
    cudaGetSymbolAddress((void**)&cl,  g_cl);
    cudaGetSymbolAddress((void**)&oh,  g_oh);
    cudaGetSymbolAddress((void**)&ol,  g_ol);
    cudaGetSymbolAddress((void**)&wqh, g_wqh);
    cudaGetSymbolAddress((void**)&wql, g_wql);
    cudaGetSymbolAddress((void**)&wkvh, g_wkvh);
    cudaGetSymbolAddress((void**)&wkvl, g_wkvl);
    cudaGetSymbolAddress((void**)&woh, g_woh);
    cudaGetSymbolAddress((void**)&wol, g_wol);
    cudaGetSymbolAddress((void**)&qb,  g_qb);
    cudaGetSymbolAddress((void**)&kbp, g_kb);
    cudaGetSymbolAddress((void**)&vrh, g_vrh);
    cudaGetSymbolAddress((void**)&vrl, g_vrl);

    cudaFuncSetAttribute(gemm_mma, cudaFuncAttributeMaxDynamicSharedMemorySize,
                         GM_SMEM_DYN);
    cudaFuncSetAttribute(gemm_qkv, cudaFuncAttributeMaxDynamicSharedMemorySize,
                         GM_SMEM_DYN);
    cudaFuncSetAttribute(ca_attn_mma, cudaFuncAttributeMaxDynamicSharedMemorySize,
                         AT_SMEM);

    // --- input conversions (2 launches) ---
    {
        int total = B_ * N_ * DIM_ + B_ * L_ * DIM_;   // 10M
        conv_split_xc<<<(total + 255) / 256, 256>>>(x, ctx, xh, xl, ch, cl);
        conv_w_t3<<<4096, dim3(32, 8)>>>(Wq, Wkv, Wout, wqh, wql,
                                         wkvh, wkvl, woh, wol);
    }

    // Q + K + V GEMMs fused into one launch (V 3-pass first for load balance)
    gemm_qkv<<<1152, 256, GM_SMEM_DYN>>>(xh, xl, ch, cl, wqh, wql, wkvh, wkvl,
                                         qb, kbp, vrh, vrl);

    // attention -> oh/ol (occ 2, single-buffer phase pipeline)
    ca_attn_mma<<<dim3(N_ / 128, HEADS_, B_), 256, AT_SMEM>>>(
        qb, kbp, vrh, vrl, sims, beta, oh, ol);

    // out = O @ Wout + bout (fp32), 3-PASS
    gemm_mma<<<dim3(DIM_ / GM_BN, (B_ * N_) / GM_BM), 256, GM_SMEM_DYN>>>(
        oh, ol, woh, wol, bout, out, B_ * N_, DIM_, DIM_, 3);
}

// round 17
// speedup vs baseline: 1.0114x; 1.0114x over previous
#include <cuda_runtime.h>
#include <cuda_bf16.h>
#include <math.h>
#include <stdint.h>

// Problem constants
#define B_     2
#define N_     1024
#define DIM_   1024
#define HEADS_ 8
#define HD_    128
#define L_     4096   // m * nc
#define M_DOCS 4

// ---------------------------------------------------------------------------
// Scratch (__device__ globals; allocation-free rule)
// ---------------------------------------------------------------------------
__device__ __nv_bfloat16 g_xh [(B_*N_) * DIM_];
__device__ __nv_bfloat16 g_xl [(B_*N_) * DIM_];
__device__ __nv_bfloat16 g_ch [(B_*L_) * DIM_];
__device__ __nv_bfloat16 g_cl [(B_*L_) * DIM_];
__device__ __nv_bfloat16 g_oh [(B_*N_) * DIM_];   // attn output, split hi
__device__ __nv_bfloat16 g_ol [(B_*N_) * DIM_];   // attn output, split lo
// weights transposed to [N,K]
__device__ __nv_bfloat16 g_wqh [DIM_ * DIM_];
__device__ __nv_bfloat16 g_wql [DIM_ * DIM_];
__device__ __nv_bfloat16 g_wkvh[(2*DIM_) * DIM_];
__device__ __nv_bfloat16 g_wkvl[(2*DIM_) * DIM_];
__device__ __nv_bfloat16 g_woh [DIM_ * DIM_];
__device__ __nv_bfloat16 g_wol [DIM_ * DIM_];

// attention operands
__device__ __nv_bfloat16 g_qb [(B_*N_) * DIM_];   // Q plain bf16
__device__ __nv_bfloat16 g_kb [(B_*L_) * DIM_];   // K plain bf16
__device__ __nv_bfloat16 g_vrh[(B_*L_) * DIM_];   // V row-major hi
__device__ __nv_bfloat16 g_vrl[(B_*L_) * DIM_];   // V row-major lo

// split-KV partials: po[half][(b*N+row)*DIM + h*128 + d], m/l per (half,h,row)
__device__ float g_po[2 * (B_*N_) * DIM_];        // 16 MB
__device__ float g_pm[2 * HEADS_ * (B_*N_)];
__device__ float g_pl[2 * HEADS_ * (B_*N_)];

// ---------------------------------------------------------------------------
// PTX helpers — ONLY non-'a' features (compute_103 PTX: no tcgen05).
// ---------------------------------------------------------------------------
#define CP_ASYNC16(dst, src) \
    asm volatile("cp.async.cg.shared.global [%0], [%1], 16;\n" \
                 :: "r"(dst), "l"(src) : "memory")
#define CP_ASYNC_COMMIT()  asm volatile("cp.async.commit_group;\n" ::: "memory")
#define CP_ASYNC_WAIT2()   asm volatile("cp.async.wait_group 2;\n" ::: "memory")
#define CP_ASYNC_WAIT1()   asm volatile("cp.async.wait_group 1;\n" ::: "memory")
#define CP_ASYNC_WAIT0()   asm volatile("cp.async.wait_group 0;\n" ::: "memory")

#define LDSM_X4(r0, r1, r2, r3, a) \
    asm volatile("ldmatrix.sync.aligned.m8n8.x4.shared.b16 {%0,%1,%2,%3}, [%4];" \
                 : "=r"(r0), "=r"(r1), "=r"(r2), "=r"(r3) : "r"(a))

#define LDSM_X4_T(r0, r1, r2, r3, a) \
    asm volatile("ldmatrix.sync.aligned.m8n8.x4.trans.shared.b16 {%0,%1,%2,%3}, [%4];" \
                 : "=r"(r0), "=r"(r1), "=r"(r2), "=r"(r3) : "r"(a))

__device__ __forceinline__ uint32_t smem_u32(const void* p) {
    uint32_t a;
    asm("{ .reg .u64 t; cvta.to.shared.u64 t, %1; cvt.u32.u64 %0, t; }"
        : "=r"(a) : "l"(p));
    return a;
}

// D += A @ B^T : m16n8k16, bf16 in, fp32 accum (layout validated R8/R10)
__device__ __forceinline__ void mma16816(float* d, const uint32_t* a,
                                         const uint32_t* b) {
    asm volatile(
        "mma.sync.aligned.m16n8k16.row.col.f32.bf16.bf16.f32 "
        "{%0,%1,%2,%3}, {%4,%5,%6,%7}, {%8,%9}, {%0,%1,%2,%3};"
        : "+f"(d[0]), "+f"(d[1]), "+f"(d[2]), "+f"(d[3])
        : "r"(a[0]), "r"(a[1]), "r"(a[2]), "r"(a[3]), "r"(b[0]), "r"(b[1]));
}

__device__ __forceinline__ uint32_t pack_bf16(float a, float b) {
    __nv_bfloat162 t = __float22bfloat162_rn(make_float2(a, b));
    return *(uint32_t*)&t;
}

// ---------------------------------------------------------------------------
// Conversion kernels — merged (2 launches)
// ---------------------------------------------------------------------------
__global__ void conv_split_xc(const float* __restrict__ x,
                              const float* __restrict__ ctx,
                              __nv_bfloat16* __restrict__ xh,
                              __nv_bfloat16* __restrict__ xl,
                              __nv_bfloat16* __restrict__ ch,
                              __nv_bfloat16* __restrict__ cl)
{
    const int tx = B_ * N_ * DIM_;
    const int tc = B_ * L_ * DIM_;
    int i = blockIdx.x * blockDim.x + threadIdx.x;
    if (i < tx) {
        float v = x[i];
        __nv_bfloat16 hi = __float2bfloat16(v);
        xh[i] = hi;
        xl[i] = __float2bfloat16(v - __bfloat162float(hi));
    } else if (i < tx + tc) {
        int j = i - tx;
        float v = ctx[j];
        __nv_bfloat16 hi = __float2bfloat16(v);
        ch[j] = hi;
        cl[j] = __float2bfloat16(v - __bfloat162float(hi));
    }
}

__global__ void conv_w_t3(const float* __restrict__ Wq,
                          const float* __restrict__ Wkv,
                          const float* __restrict__ Wout,
                          __nv_bfloat16* __restrict__ wqh,
                          __nv_bfloat16* __restrict__ wql,
                          __nv_bfloat16* __restrict__ wkvh,
                          __nv_bfloat16* __restrict__ wkvl,
                          __nv_bfloat16* __restrict__ woh,
                          __nv_bfloat16* __restrict__ wol)
{
    __shared__ float t[32][33];
    int id = blockIdx.x;
    const float* W; __nv_bfloat16 *Wh, *Wl; int N, tile;
    if (id < 1024)      { W = Wq;   Wh = wqh;  Wl = wql;  N = DIM_;     tile = id; }
    else if (id < 3072) { W = Wkv;  Wh = wkvh; Wl = wkvl; N = 2 * DIM_; tile = id - 1024; }
    else                { W = Wout; Wh = woh;  Wl = wol;  N = DIM_;     tile = id - 3072; }
    const int K = DIM_;
    int nx = N / 32;
    int n0 = (tile % nx) * 32, k0 = (tile / nx) * 32;
    int tx = threadIdx.x, ty = threadIdx.y;
    #pragma unroll
    for (int i = 0; i < 32; i += 8)
        t[ty + i][tx] = W[(size_t)(k0 + ty + i) * N + n0 + tx];
    __syncthreads();
    #pragma unroll
    for (int i = 0; i < 32; i += 8) {
        float v = t[tx][ty + i];
        __nv_bfloat16 hi = __float2bfloat16(v);
        size_t o = (size_t)(n0 + ty + i) * K + k0 + tx;
        Wh[o] = hi;
        Wl[o] = __float2bfloat16(v - __bfloat162float(hi));
    }
}

// ---------------------------------------------------------------------------
// GEMM core (unchanged — validated)
// ---------------------------------------------------------------------------
#define GM_BM  128
#define GM_BN  128
#define GM_BK  64
#define GM_LDA 72
#define GM_STAGE_ELEMS ((GM_BM + GM_BN) * GM_LDA)
#define GM_SMEM_DYN (2 * GM_STAGE_ELEMS * 2)

__device__ __forceinline__ void gemm_core(
    const __nv_bfloat16* __restrict__ Ah, const __nv_bfloat16* __restrict__ Al,
    const __nv_bfloat16* __restrict__ Bh, const __nv_bfloat16* __restrict__ Bl,
    const float* __restrict__ bias, float* __restrict__ C,
    __nv_bfloat16* __restrict__ Cb,
    __nv_bfloat16* __restrict__ vrh, __nv_bfloat16* __restrict__ vrl,
    int M, int N, int K, int mode, int npasses, int m0, int n0,
    __nv_bfloat16* dsm)
{
    const int tid   = threadIdx.x;
    const int wid   = tid >> 5;
    const int lane  = tid & 31;
    const int g     = lane >> 2;
    const int t4    = lane & 3;
    const int warpM = wid & 3;
    const int warpN = wid >> 2;
    const int KB = K * 2;
    const int kchunks = K / GM_BK;
    const int NCHUNK = npasses * kchunks;

    const uint32_t smem_base = smem_u32(dsm);

    const uint32_t aOff = (uint32_t)(warpM * 32 + (lane & 15)) * (GM_LDA * 2)
                        + ((lane >> 4) << 3) * 2;
    const uint32_t bOff = (uint32_t)(warpN * 64 + ((lane & 16) >> 1) + (lane & 7))
                        * (GM_LDA * 2) + ((lane & 8) ? 16 : 0);

    float acc[2][8][4];
    #pragma unroll
    for (int mi = 0; mi < 2; mi++)
        #pragma unroll
        for (int ni = 0; ni < 8; ni++)
            #pragma unroll
            for (int r = 0; r < 4; r++) acc[mi][ni][r] = 0.f;

    auto load_tile = [&](int s, int c) {
        int pass = c / kchunks;
        int kc   = c - pass * kchunks;
        const char* Asrc = (const char*)((pass < 2) ? Ah : Al)
                         + (size_t)m0 * KB + (size_t)kc * (GM_BK * 2);
        const char* Bsrc = (const char*)((pass == 1) ? Bl : Bh)
                         + (size_t)n0 * KB + (size_t)kc * (GM_BK * 2);
        uint32_t As = smem_base + s * (GM_STAGE_ELEMS * 2);
        uint32_t Bs = As + GM_BM * GM_LDA * 2;
        #pragma unroll
        for (int i = 0; i < 8; i++) {
            int u = tid + i * 256;
            if (i < 4) {
                int row = u >> 3, ch = u & 7;
                CP_ASYNC16(As + row * (GM_LDA * 2) + ch * 16,
                           Asrc + (size_t)row * KB + ch * 16);
            } else {
                int v = u - 1024;
                int row = v >> 3, ch = v & 7;
                CP_ASYNC16(Bs + row * (GM_LDA * 2) + ch * 16,
                           Bsrc + (size_t)row * KB + ch * 16);
            }
        }
        CP_ASYNC_COMMIT();
    };

    load_tile(0, 0);

    for (int c = 0; c < NCHUNK; c++) {
        if (c + 1 < NCHUNK) {
            load_tile((c + 1) & 1, c + 1);
            CP_ASYNC_WAIT1();
        } else {
            CP_ASYNC_WAIT0();
        }
        __syncthreads();

        uint32_t As = smem_base + (c & 1) * (GM_STAGE_ELEMS * 2);
        uint32_t Bs = As + GM_BM * GM_LDA * 2;
        uint32_t aAddr = As + aOff;
        uint32_t bAddr = Bs + bOff;

        #pragma unroll
        for (int kk = 0; kk < GM_BK; kk += 16) {
            uint32_t af[2][4], bfr[8][2];
            #pragma unroll
            for (int mi = 0; mi < 2; mi++)
                LDSM_X4(af[mi][0], af[mi][1], af[mi][2], af[mi][3],
                        aAddr + kk * 2 + mi * 16 * (GM_LDA * 2));
            #pragma unroll
            for (int pr = 0; pr < 4; pr++)
                LDSM_X4(bfr[2*pr][0], bfr[2*pr][1], bfr[2*pr+1][0], bfr[2*pr+1][1],
                        bAddr + kk * 2 + pr * 16 * (GM_LDA * 2));
            #pragma unroll
            for (int mi = 0; mi < 2; mi++)
                #pragma unroll
                for (int ni = 0; ni < 8; ni++)
                    mma16816(acc[mi][ni], af[mi], bfr[ni]);
        }
        __syncthreads();
    }

    #pragma unroll
    for (int mi = 0; mi < 2; mi++) {
        int rowA = m0 + warpM * 32 + mi * 16 + g;
        #pragma unroll
        for (int ni = 0; ni < 8; ni++) {
            int col = n0 + warpN * 64 + ni * 8 + 2 * t4;
            #pragma unroll
            for (int half = 0; half < 2; half++) {
                int row = rowA + half * 8;
                float v0 = acc[mi][ni][half * 2 + 0];
                float v1 = acc[mi][ni][half * 2 + 1];
                if (mode == 0) {
                    *(float2*)(C + (size_t)row * N + col) =
                        make_float2(v0 + bias[col], v1 + bias[col + 1]);
                } else if (mode == 1) {
                    *(uint32_t*)(Cb + (size_t)row * N + col) = pack_bf16(v0, v1);
                } else {
                    size_t off = (size_t)row * N + col;
                    __nv_bfloat16 h0 = __float2bfloat16(v0);
                    __nv_bfloat16 h1 = __float2bfloat16(v1);
                    __nv_bfloat162 hp; hp.x = h0; hp.y = h1;
                    *(uint32_t*)(vrh + off) = *(uint32_t*)&hp;
                    *(uint32_t*)(vrl + off) =
                        pack_bf16(v0 - __bfloat162float(h0),
                                  v1 - __bfloat162float(h1));
                }
            }
        }
    }
}

__global__ __launch_bounds__(256, 2)
void gemm_mma(const __nv_bfloat16* __restrict__ Ah,
              const __nv_bfloat16* __restrict__ Al,
              const __nv_bfloat16* __restrict__ Bh,
              const __nv_bfloat16* __restrict__ Bl,
              const float* __restrict__ bias, float* __restrict__ C,
              int M, int N, int K, int npasses)
{
    extern __shared__ __align__(16) __nv_bfloat16 dsm[];
    gemm_core(Ah, Al, Bh, Bl, bias, C, nullptr, nullptr, nullptr,
              M, N, K, 0, npasses, blockIdx.y * GM_BM, blockIdx.x * GM_BN, dsm);
}

__global__ __launch_bounds__(256, 2)
void gemm_qkv(const __nv_bfloat16* __restrict__ xh,
              const __nv_bfloat16* __restrict__ xl,
              const __nv_bfloat16* __restrict__ ch,
              const __nv_bfloat16* __restrict__ cl,
              const __nv_bfloat16* __restrict__ wqh,
              const __nv_bfloat16* __restrict__ wql,
              const __nv_bfloat16* __restrict__ wkvh,
              const __nv_bfloat16* __restrict__ wkvl,
              __nv_bfloat16* __restrict__ qb,
              __nv_bfloat16* __restrict__ kb,
              __nv_bfloat16* __restrict__ vrh,
              __nv_bfloat16* __restrict__ vrl)
{
    extern __shared__ __align__(16) __nv_bfloat16 dsm[];
    int id = blockIdx.x;
    if (id < 512) {                     // V: 3-pass, split row-major out
        int m0 = (id >> 3) * GM_BM, n0 = (id & 7) * GM_BN;
        gemm_core(ch, cl, wkvh + (size_t)DIM_ * DIM_, wkvl + (size_t)DIM_ * DIM_,
                  nullptr, nullptr, nullptr, vrh, vrl,
                  B_ * L_, DIM_, DIM_, 2, 3, m0, n0, dsm);
    } else if (id < 1024) {             // K: 1-pass, plain bf16
        int t = id - 512;
        int m0 = (t >> 3) * GM_BM, n0 = (t & 7) * GM_BN;
        gemm_core(ch, cl, wkvh, wkvl, nullptr, nullptr, kb, nullptr, nullptr,
                  B_ * L_, DIM_, DIM_, 1, 1, m0, n0, dsm);
    } else {                            // Q: 1-pass, plain bf16
        int t = id - 1024;
        int m0 = (t >> 3) * GM_BM, n0 = (t & 7) * GM_BN;
        gemm_core(xh, xl, wqh, wql, nullptr, nullptr, qb, nullptr, nullptr,
                  B_ * N_, DIM_, DIM_, 1, 1, m0, n0, dsm);
    }
}

// ---------------------------------------------------------------------------
// SPLIT-KV flash attention: grid (8 qt, 8 h, 4 = b*2+half) = 256 CTAs, occ 2.
// Each CTA sweeps 32 of the 64 key tiles and writes UNNORMALIZED partial O
// (fp32) + per-row (m, l).  Smem 104 KB: Q + double-K + single-V.
// Pipeline: K(t+1) prefetched into spare buffer at iter start; V(t+1)
// loaded after PV(t).  Queue invariant -> waitK=wait_group 2, waitV=1.
// ---------------------------------------------------------------------------
#define AT_LD   136
#define AT_SMEM ((128*AT_LD + 2*64*AT_LD + 2*64*AT_LD) * 2)   // 104448 B
#define AT_TILES 32

__global__ __launch_bounds__(256, 2)
void ca_attn_mma(const __nv_bfloat16* __restrict__ qb,
                 const __nv_bfloat16* __restrict__ kb,
                 const __nv_bfloat16* __restrict__ vrh,
                 const __nv_bfloat16* __restrict__ vrl,
                 const float* __restrict__ sims,
                 const float* __restrict__ beta_p,
                 float* __restrict__ po,
                 float* __restrict__ pm,
                 float* __restrict__ pl)
{
    extern __shared__ __align__(16) __nv_bfloat16 smattn[];
    const uint32_t sQ   = smem_u32(smattn);
    const uint32_t sKb  = sQ  + 128 * AT_LD * 2;     // two 64-row K stages
    const uint32_t sVh  = sKb + 2 * 64 * AT_LD * 2;
    const uint32_t sVl  = sVh + 64 * AT_LD * 2;

    const int qt = blockIdx.x, h = blockIdx.y;
    const int b = blockIdx.z >> 1, half = blockIdx.z & 1;
    const int kt0 = half * AT_TILES;
    const int tid = threadIdx.x, wid = tid >> 5, lane = tid & 31;
    const int g = lane >> 2, t4 = lane & 3;
    const float beta = beta_p[0];
    const int qrow0 = b * N_ + qt * 128;

    const uint32_t qOff = (uint32_t)(wid * 16 + (lane & 15)) * (AT_LD * 2)
                        + ((lane >> 4) << 3) * 2;
    const uint32_t kOff = (uint32_t)(((lane & 16) >> 1) + (lane & 7)) * (AT_LD * 2)
                        + ((lane & 8) ? 16 : 0);
    const uint32_t vOffT = (uint32_t)(((lane & 8) ? 8 : 0) + (lane & 7)) * (AT_LD * 2)
                         + ((lane & 16) ? 16 : 0);

    // Q load (group)
    #pragma unroll
    for (int i = 0; i < 8; i++) {
        int u = tid + i * 256, r = u >> 4, ch = u & 15;
        CP_ASYNC16(sQ + r * (AT_LD * 2) + ch * 16,
                   (const char*)qb + ((size_t)(qrow0 + r) * DIM_ + h * HD_) * 2 + ch * 16);
    }
    CP_ASYNC_COMMIT();

    auto load_k = [&](int tloc) {
        uint32_t dst = sKb + (tloc & 1) * 64 * AT_LD * 2;
        const size_t krow0 = (size_t)(b * L_ + (kt0 + tloc) * 64);
        #pragma unroll
        for (int i = 0; i < 4; i++) {
            int u = tid + i * 256, r = u >> 4, ch = u & 15;
            CP_ASYNC16(dst + r * (AT_LD * 2) + ch * 16,
                       (const char*)kb + ((krow0 + r) * DIM_ + h * HD_) * 2 + ch * 16);
        }
        CP_ASYNC_COMMIT();
    };
    auto load_v = [&](int tloc) {
        const size_t krow0 = (size_t)(b * L_ + (kt0 + tloc) * 64);
        #pragma unroll
        for (int i = 0; i < 4; i++) {
            int u = tid + i * 256, r = u >> 4, ch = u & 15;
            CP_ASYNC16(sVh + r * (AT_LD * 2) + ch * 16,
                       (const char*)vrh + ((krow0 + r) * DIM_ + h * HD_) * 2 + ch * 16);
        }
        #pragma unroll
        for (int i = 0; i < 4; i++) {
            int u = tid + i * 256, r = u >> 4, ch = u & 15;
            CP_ASYNC16(sVl + r * (AT_LD * 2) + ch * 16,
                       (const char*)vrl + ((krow0 + r) * DIM_ + h * HD_) * 2 + ch * 16);
        }
        CP_ASYNC_COMMIT();
    };

    load_k(0);
    load_v(0);

    float o[16][4];
    #pragma unroll
    for (int nj = 0; nj < 16; nj++)
        #pragma unroll
        for (int r = 0; r < 4; r++) o[nj][r] = 0.f;
    float m0r = -3.0e38f, m1r = -3.0e38f, l0r = 0.f, l1r = 0.f;

    for (int tloc = 0; tloc < AT_TILES; tloc++) {
        // prefetch next K into the spare buffer (no dependency on current K)
        if (tloc + 1 < AT_TILES) load_k(tloc + 1);
        // wait K(tloc):
        //   tloc=0: queue {Q,K0,V0,K1} -> wait 2 drains Q,K0
        //   1<=t<31: queue {K(t),V(t),K(t+1)} -> wait 2 drains K(t)
        //   t=31:  queue {K31,V31} -> wait 1 drains K31
        if (tloc + 1 < AT_TILES) CP_ASYNC_WAIT2(); else CP_ASYNC_WAIT1();
        __syncthreads();

        uint32_t sK = sKb + (tloc & 1) * 64 * AT_LD * 2;

        // ---- S = Q @ K^T ----
        float s[8][4];
        #pragma unroll
        for (int nj = 0; nj < 8; nj++)
            #pragma unroll
            for (int r = 0; r < 4; r++) s[nj][r] = 0.f;

        #pragma unroll
        for (int kk = 0; kk < 128; kk += 16) {
            uint32_t af[4], bfr[8][2];
            LDSM_X4(af[0], af[1], af[2], af[3], sQ + qOff + kk * 2);
            #pragma unroll
            for (int pr = 0; pr < 4; pr++)
                LDSM_X4(bfr[2*pr][0], bfr[2*pr][1], bfr[2*pr+1][0], bfr[2*pr+1][1],
                        sK + kOff + kk * 2 + pr * 16 * (AT_LD * 2));
            #pragma unroll
            for (int nj = 0; nj < 8; nj++)
                mma16816(s[nj], af, bfr[nj]);
        }

        // ---- online softmax (registers only) ----
        const float simv = sims[b * M_DOCS + ((kt0 + tloc) >> 4)] * beta;
        float lg[8][4];
        float mt0 = -3.0e38f, mt1 = -3.0e38f;
        #pragma unroll
        for (int nj = 0; nj < 8; nj++) {
            lg[nj][0] = s[nj][0] * 0.03125f + simv;
            lg[nj][1] = s[nj][1] * 0.03125f + simv;
            lg[nj][2] = s[nj][2] * 0.03125f + simv;
            lg[nj][3] = s[nj][3] * 0.03125f + simv;
            mt0 = fmaxf(mt0, fmaxf(lg[nj][0], lg[nj][1]));
            mt1 = fmaxf(mt1, fmaxf(lg[nj][2], lg[nj][3]));
        }
        mt0 = fmaxf(mt0, __shfl_xor_sync(0xffffffffu, mt0, 1, 4));
        mt0 = fmaxf(mt0, __shfl_xor_sync(0xffffffffu, mt0, 2, 4));
        mt1 = fmaxf(mt1, __shfl_xor_sync(0xffffffffu, mt1, 1, 4));
        mt1 = fmaxf(mt1, __shfl_xor_sync(0xffffffffu, mt1, 2, 4));
        float mn0 = fmaxf(m0r, mt0), mn1 = fmaxf(m1r, mt1);
        float c0 = __expf(m0r - mn0), c1 = __expf(m1r - mn1);
        m0r = mn0; m1r = mn1; l0r *= c0; l1r *= c1;
        #pragma unroll
        for (int nj = 0; nj < 16; nj++) {
            o[nj][0] *= c0; o[nj][1] *= c0;
            o[nj][2] *= c1; o[nj][3] *= c1;
        }

        uint32_t ph01[8], ph23[8], pl01[8], pl23[8];
        #pragma unroll
        for (int nj = 0; nj < 8; nj++) {
            float p0 = __expf(lg[nj][0] - mn0), p1 = __expf(lg[nj][1] - mn0);
            float p2 = __expf(lg[nj][2] - mn1), p3 = __expf(lg[nj][3] - mn1);
            l0r += p0 + p1; l1r += p2 + p3;
            __nv_bfloat162 h01 = __float22bfloat162_rn(make_float2(p0, p1));
            __nv_bfloat162 h23 = __float22bfloat162_rn(make_float2(p2, p3));
            float2 b01 = __bfloat1622float2(h01);
            float2 b23 = __bfloat1622float2(h23);
            ph01[nj] = *(uint32_t*)&h01;
            ph23[nj] = *(uint32_t*)&h23;
            pl01[nj] = pack_bf16(p0 - b01.x, p1 - b01.y);
            pl23[nj] = pack_bf16(p2 - b23.x, p3 - b23.y);
        }

        // wait V(tloc): queue {V(t), K(t+1)} -> wait 1; tail -> wait 0
        if (tloc + 1 < AT_TILES) CP_ASYNC_WAIT1(); else CP_ASYNC_WAIT0();
        __syncthreads();

        // ---- O += ph*Vh + ph*Vl + pl*Vh ----
        #pragma unroll
        for (int kbi = 0; kbi < 4; kbi++) {
            uint32_t ah[4] = { ph01[2*kbi], ph23[2*kbi], ph01[2*kbi+1], ph23[2*kbi+1] };
            uint32_t al[4] = { pl01[2*kbi], pl23[2*kbi], pl01[2*kbi+1], pl23[2*kbi+1] };
            #pragma unroll
            for (int pr = 0; pr < 8; pr++) {
                uint32_t bh2[2], bh2b[2], bl2[2], bl2b[2];
                uint32_t adrH = sVh + vOffT + (kbi * 16) * (AT_LD * 2) + pr * 32;
                uint32_t adrL = sVl + vOffT + (kbi * 16) * (AT_LD * 2) + pr * 32;
                LDSM_X4_T(bh2[0], bh2[1], bh2b[0], bh2b[1], adrH);
                LDSM_X4_T(bl2[0], bl2[1], bl2b[0], bl2b[1], adrL);
                mma16816(o[2*pr],     ah, bh2);
                mma16816(o[2*pr],     ah, bl2);
                mma16816(o[2*pr],     al, bh2);
                mma16816(o[2*pr + 1], ah, bh2b);
                mma16816(o[2*pr + 1], ah, bl2b);
                mma16816(o[2*pr + 1], al, bh2b);
            }
        }
        __syncthreads();                       // all warps done reading V
        if (tloc + 1 < AT_TILES) load_v(tloc + 1);
    }

    // partial epilogue: quad-reduce l, write UNNORMALIZED o + (m, l)
    l0r += __shfl_xor_sync(0xffffffffu, l0r, 1, 4);
    l0r += __shfl_xor_sync(0xffffffffu, l0r, 2, 4);
    l1r += __shfl_xor_sync(0xffffffffu, l1r, 1, 4);
    l1r += __shfl_xor_sync(0xffffffffu, l1r, 2, 4);

    float* poH = po + (size_t)half * (B_ * N_) * DIM_;
    const int rml0 = qrow0 + wid * 16 + g;       // b*N + qt*128 + warp row
    const size_t ob0 = (size_t)rml0 * DIM_ + h * HD_;
    const size_t ob1 = (size_t)(rml0 + 8) * DIM_ + h * HD_;
    #pragma unroll
    for (int nj = 0; nj < 16; nj++) {
        int col = nj * 8 + 2 * t4;
        *(float2*)(poH + ob0 + col) = make_float2(o[nj][0], o[nj][1]);
        *(float2*)(poH + ob1 + col) = make_float2(o[nj][2], o[nj][3]);
    }
    if (t4 == 0) {
        int mb = (half * HEADS_ + h) * (B_ * N_);
        pm[mb + rml0]     = m0r;  pl[mb + rml0]     = l0r;
        pm[mb + rml0 + 8] = m1r;  pl[mb + rml0 + 8] = l1r;
    }
}

// combine the two KV-halves: exact FA merge, write split-bf16 oh/ol
__global__ void attn_combine(const float* __restrict__ po,
                             const float* __restrict__ pm,
                             const float* __restrict__ pl,
                             __nv_bfloat16* __restrict__ Oh,
                             __nv_bfloat16* __restrict__ Ol)
{
    const int qt = blockIdx.x, h = blockIdx.y, b = blockIdx.z;
    const size_t HALFSZ = (size_t)(B_ * N_) * DIM_;
    const int mb0 = h * (B_ * N_);
    const int mb1 = (HEADS_ + h) * (B_ * N_);
    for (int e = threadIdx.x; e < 128 * 64; e += 256) {
        int row = e >> 6, dp = (e & 63) * 2;
        int rml = b * N_ + qt * 128 + row;
        size_t off = (size_t)rml * DIM_ + h * HD_ + dp;
        float m1 = pm[mb0 + rml], m2 = pm[mb1 + rml];
        float l1 = pl[mb0 + rml], l2 = pl[mb1 + rml];
        float M = fmaxf(m1, m2);
        float w1 = __expf(m1 - M), w2 = __expf(m2 - M);
        float inv = 1.0f / (l1 * w1 + l2 * w2);
        float2 a = *(const float2*)(po + off);
        float2 c = *(const float2*)(po + HALFSZ + off);
        float v0 = (a.x * w1 + c.x * w2) * inv;
        float v1 = (a.y * w1 + c.y * w2) * inv;
        __nv_bfloat162 hi2;
        hi2.x = __float2bfloat16(v0);
        hi2.y = __float2bfloat16(v1);
        *(uint32_t*)(Oh + off) = *(uint32_t*)&hi2;
        *(uint32_t*)(Ol + off) =
            pack_bf16(v0 - __bfloat162float(hi2.x),
                      v1 - __bfloat162float(hi2.y));
    }
}

// ---------------------------------------------------------------------------
extern "C" void kernel_launch(void* const* d_in, const int* in_sizes, int n_in,
                              void* d_out, int out_size)
{
    const float* x    = (const float*)d_in[0];
    const float* ctx  = (const float*)d_in[1];
    const float* sims = (const float*)d_in[2];
    const float* Wq   = (const float*)d_in[3];
    const float* Wkv  = (const float*)d_in[4];
    const float* beta = (const float*)d_in[5];
    const float* Wout = (const float*)d_in[6];
    const float* bout = (const float*)d_in[7];
    float* out = (float*)d_out;

    __nv_bfloat16 *xh, *xl, *ch, *cl, *oh, *ol;
    __nv_bfloat16 *wqh, *wql, *wkvh, *wkvl, *woh, *wol;
    __nv_bfloat16 *qb, *kbp, *vrh, *vrl;
    float *po, *pmp, *plp;
    cudaGetSymbolAddress((void**)&xh,  g_xh);
    cudaGetSymbolAddress((void**)&xl,  g_xl);
    cudaGetSymbolAddress((void**)&ch,  g_ch);
    cudaGetSymbolAddress((void**)&cl,  g_cl);
    cudaGetSymbolAddress((void**)&oh,  g_oh);
    cudaGetSymbolAddress((void**)&ol,  g_ol);
    cudaGetSymbolAddress((void**)&wqh, g_wqh);
    cudaGetSymbolAddress((void**)&wql, g_wql);
    cudaGetSymbolAddress((void**)&wkvh, g_wkvh);
    cudaGetSymbolAddress((void**)&wkvl, g_wkvl);
    cudaGetSymbolAddress((void**)&woh, g_woh);
    cudaGetSymbolAddress((void**)&wol, g_wol);
    cudaGetSymbolAddress((void**)&qb,  g_qb);
    cudaGetSymbolAddress((void**)&kbp, g_kb);
    cudaGetSymbolAddress((void**)&vrh, g_vrh);
    cudaGetSymbolAddress((void**)&vrl, g_vrl);
    cudaGetSymbolAddress((void**)&po,  g_po);
    cudaGetSymbolAddress((void**)&pmp, g_pm);
    cudaGetSymbolAddress((void**)&plp, g_pl);

    cudaFuncSetAttribute(gemm_mma, cudaFuncAttributeMaxDynamicSharedMemorySize,
                         GM_SMEM_DYN);
    cudaFuncSetAttribute(gemm_qkv, cudaFuncAttributeMaxDynamicSharedMemorySize,
                         GM_SMEM_DYN);
    cudaFuncSetAttribute(ca_attn_mma, cudaFuncAttributeMaxDynamicSharedMemorySize,
                         AT_SMEM);

    // --- input conversions (2 launches) ---
    {
        int total = B_ * N_ * DIM_ + B_ * L_ * DIM_;
        conv_split_xc<<<(total + 255) / 256, 256>>>(x, ctx, xh, xl, ch, cl);
        conv_w_t3<<<4096, dim3(32, 8)>>>(Wq, Wkv, Wout, wqh, wql,
                                         wkvh, wkvl, woh, wol);
    }

    // Q + K + V GEMMs fused into one launch
    gemm_qkv<<<1152, 256, GM_SMEM_DYN>>>(xh, xl, ch, cl, wqh, wql, wkvh, wkvl,
                                         qb, kbp, vrh, vrl);

    // split-KV attention: 256 CTAs, occ 2 — partials to po/pm/pl
    ca_attn_mma<<<dim3(N_ / 128, HEADS_, B_ * 2), 256, AT_SMEM>>>(
        qb, kbp, vrh, vrl, sims, beta, po, pmp, plp);

    // merge halves -> oh/ol (split bf16)
    attn_combine<<<dim3(N_ / 128, HEADS_, B_), 256>>>(po, pmp, plp, oh, ol);

    // out = O @ Wout + bout (fp32), 3-PASS
    gemm_mma<<<dim3(DIM_ / GM_BN, (B_ * N_) / GM_BM), 256, GM_SMEM_DYN>>>(
        oh, ol, woh, wol, bout, out, B_ * N_, DIM_, DIM_, 3);
}